// round 1
// baseline (speedup 1.0000x reference)
#include <cuda_runtime.h>
#include <math.h>

#define B   16
#define C   256
#define H   128
#define Wd  128
#define HW  16384
#define PO  20
#define NP  400
#define MID 16
#define OC  32
#define OH  64
#define OW  64

// ---------------- scratch (device globals; no allocations) ----------------
__device__ float g_xp[(size_t)B*C*NP];        // pooled (b,c,400)
__device__ float g_s[B*NP];                   // centered row means s[b,n]
__device__ float g_feat[B*C];
__device__ float g_attn[B*C];
__device__ int   g_maxid[MID];
__device__ float g_scale[MID];
__device__ float g_xc[(size_t)B*OC*HW];       // concat channels (in-place -> xa)
__device__ float g_sp[(size_t)B*2*HW];        // mean/max spatial maps
__device__ float g_y[(size_t)B*OC*OH*OW];     // conv output pre-BN
__device__ float g_bnsum[OC], g_bnsum2[OC];
__device__ float g_bns[OC], g_bnb[OC];

// ---------------- 1. adaptive avg pool 128x128 -> 20x20 ----------------
__global__ void k_pool(const float* __restrict__ x) {
    int bc = blockIdx.x;                       // b*C + c
    const float* src = x + (size_t)bc * HW;
    for (int o = threadIdx.x; o < NP; o += blockDim.x) {
        int oh = o / PO, ow = o % PO;
        int hs = (oh * H) / PO,  he = ((oh + 1) * H + PO - 1) / PO;
        int ws = (ow * Wd) / PO, we = ((ow + 1) * Wd + PO - 1) / PO;
        float acc = 0.f;
        for (int hh = hs; hh < he; hh++) {
            const float* r = src + hh * Wd;
            for (int ww = ws; ww < we; ww++) acc += r[ww];
        }
        g_xp[(size_t)bc * NP + o] = acc / (float)((he - hs) * (we - ws));
    }
}

// ---------------- 2a. s[b,n] = rowmean - globalmean ----------------
__global__ void k_svec() {
    __shared__ float sh[512];
    int b = blockIdx.x, t = threadIdx.x;
    float acc = 0.f;
    if (t < NP) {
        const float* p = &g_xp[(size_t)b * C * NP + t];
        for (int c = 0; c < C; c++) acc += p[(size_t)c * NP];
    }
    sh[t] = (t < NP) ? acc : 0.f;
    __syncthreads();
    for (int s = 256; s > 0; s >>= 1) {
        if (t < s) sh[t] += sh[t + s];
        __syncthreads();
    }
    float g = sh[0] / (float)(NP * C);
    if (t < NP) g_s[b * NP + t] = acc * (1.f / C) - g;
}

// ---------------- 2b. feat[b,c] = (1/399) sum_n xp[b,c,n]*s[b,n] ----------------
__global__ void k_feat() {
    int gw = (blockIdx.x * 256 + threadIdx.x) >> 5;
    int lane = threadIdx.x & 31;
    int b = gw >> 8, c = gw & 255;
    const float* xpv = &g_xp[(size_t)(b * C + c) * NP];
    const float* sv  = &g_s[b * NP];
    float acc = 0.f;
    for (int n = lane; n < NP; n += 32) acc += xpv[n] * sv[n];
    #pragma unroll
    for (int o = 16; o; o >>= 1) acc += __shfl_down_sync(0xffffffffu, acc, o);
    if (!lane) g_feat[b * C + c] = acc * (1.f / 399.f);
}

// ---------------- 2c. attn = sigmoid(feat @ W^T + b) ----------------
__global__ void k_attn(const float* __restrict__ lw, const float* __restrict__ lb) {
    int gw = (blockIdx.x * 256 + threadIdx.x) >> 5;
    int lane = threadIdx.x & 31;
    int b = gw >> 8, co = gw & 255;
    const float* f = &g_feat[b * C];
    const float* w = &lw[(size_t)co * C];
    float acc = 0.f;
    for (int c = lane; c < C; c += 32) acc += f[c] * w[c];
    #pragma unroll
    for (int o = 16; o; o >>= 1) acc += __shfl_down_sync(0xffffffffu, acc, o);
    if (!lane) {
        float z = acc + lb[co];
        g_attn[b * C + co] = 1.f / (1.f + expf(-z));
    }
}

// ---------------- 3. score mean, stable top-16 select, ascending indices ----------------
__global__ void k_select() {
    __shared__ float sc[C];
    __shared__ int sel[C];
    int c = threadIdx.x;
    float a = 0.f;
    for (int b = 0; b < B; b++) a += g_attn[b * C + c];
    float my = a * (1.f / B);
    sc[c] = my;
    __syncthreads();
    int rank = 0;
    for (int j = 0; j < C; j++) {
        float v = sc[j];
        if (v > my || (v == my && j < c)) rank++;
    }
    sel[c] = (rank < MID) ? 1 : 0;
    __syncthreads();
    if (sel[c]) {
        int pos = 0;
        for (int j = 0; j < c; j++) pos += sel[j];
        g_maxid[pos] = c;
        g_scale[pos] = 1.f + my;
    }
}

// ---------------- 4. build xc (x1 gather*scale + grouped mean) + mean/max maps ----------------
__global__ void k_xc(const float* __restrict__ x) {
    __shared__ int   mid[MID];
    __shared__ float msc[MID];
    int tid = threadIdx.x;
    if (tid < MID) { mid[tid] = g_maxid[tid]; msc[tid] = g_scale[tid]; }
    __syncthreads();
    int p = blockIdx.x * 256 + tid;
    int b = p >> 14, pix = p & 16383;
    const float* xb = x + (size_t)b * C * HW + pix;
    float vals[32];
    #pragma unroll
    for (int k = 0; k < MID; k++) vals[k] = xb[(size_t)mid[k] * HW] * msc[k];
    #pragma unroll
    for (int k = 0; k < MID; k++) {
        float a = 0.f;
        #pragma unroll
        for (int j = 0; j < 16; j++) a += xb[(size_t)(k * 16 + j) * HW];
        vals[16 + k] = a * (1.f / 16.f);
    }
    float mn = 0.f, mx = -3.4e38f;
    size_t base = (size_t)b * OC * HW + pix;
    #pragma unroll
    for (int k = 0; k < 32; k++) {
        float v = vals[k];
        mn += v;
        mx = fmaxf(mx, v);
        g_xc[base + (size_t)k * HW] = v;
    }
    g_sp[((size_t)b * 2) * HW + pix]     = mn * (1.f / 32.f);
    g_sp[((size_t)b * 2 + 1) * HW + pix] = mx;
}

// ---------------- 5. LSA 7x7 conv + sigmoid, apply in-place to xc ----------------
__global__ void k_lsa(const float* __restrict__ lw) {
    __shared__ float st[2 * 22 * 22];
    __shared__ float wsh[98];
    int b = blockIdx.z;
    int h0 = blockIdx.y * 16, w0 = blockIdx.x * 16;
    int tx = threadIdx.x, ty = threadIdx.y;
    int tid = ty * 16 + tx;
    if (tid < 98) wsh[tid] = lw[tid];
    for (int i = tid; i < 2 * 22 * 22; i += 256) {
        int ci = i / 484, r = i % 484;
        int hh = h0 + r / 22 - 3, ww = w0 + r % 22 - 3;
        float v = 0.f;
        if (hh >= 0 && hh < H && ww >= 0 && ww < Wd)
            v = g_sp[((size_t)(b * 2 + ci)) * HW + hh * Wd + ww];
        st[i] = v;
    }
    __syncthreads();
    float a = 0.f;
    #pragma unroll
    for (int ci = 0; ci < 2; ci++)
        #pragma unroll
        for (int kh = 0; kh < 7; kh++)
            #pragma unroll
            for (int kw = 0; kw < 7; kw++)
                a += st[ci * 484 + (ty + kh) * 22 + (tx + kw)] * wsh[ci * 49 + kh * 7 + kw];
    float sg = 1.f / (1.f + expf(-a));
    int pix = (h0 + ty) * Wd + (w0 + tx);
    size_t base = (size_t)b * OC * HW + pix;
    #pragma unroll
    for (int k = 0; k < OC; k++) g_xc[base + (size_t)k * HW] *= sg;
}

// ---------------- 6a. zero BN accumulators ----------------
__global__ void k_zero() {
    if (threadIdx.x < OC) { g_bnsum[threadIdx.x] = 0.f; g_bnsum2[threadIdx.x] = 0.f; }
}

// ---------------- 6b. 3x3 stride-2 pad-1 conv (+bias) + BN partial sums ----------------
__global__ void k_conv(const float* __restrict__ cw, const float* __restrict__ cb) {
    __shared__ float ws[288 * 32];    // transposed weights: [(ic*9+k)*32 + oc]
    __shared__ float tile[8 * 289];   // 8 in-channels x 17x17
    __shared__ float ssum[OC], ssum2[OC];
    int tid = threadIdx.x;
    int b = blockIdx.z;
    int oh0 = blockIdx.y * 8, ow0 = blockIdx.x * 8;
    for (int i = tid; i < 9216; i += 256) {
        int oc_ = i / 288, r = i % 288;
        ws[r * 32 + oc_] = cw[i];
    }
    if (tid < OC) { ssum[tid] = 0.f; ssum2[tid] = 0.f; }
    int oc = tid & 31, orow = tid >> 5;
    float bias = cb[oc];
    float acc[8];
    #pragma unroll
    for (int j = 0; j < 8; j++) acc[j] = bias;
    int ih0 = 2 * oh0 - 1, iw0 = 2 * ow0 - 1;
    for (int ic0 = 0; ic0 < 32; ic0 += 8) {
        __syncthreads();
        for (int i = tid; i < 8 * 289; i += 256) {
            int icl = i / 289, r = i % 289;
            int ih = ih0 + r / 17, iw = iw0 + r % 17;
            float v = 0.f;
            if (ih >= 0 && ih < H && iw >= 0 && iw < Wd)
                v = g_xc[((size_t)(b * OC + ic0 + icl)) * HW + ih * Wd + iw];
            tile[i] = v;
        }
        __syncthreads();
        #pragma unroll
        for (int icl = 0; icl < 8; icl++) {
            const float* tr = &tile[icl * 289];
            #pragma unroll
            for (int kh = 0; kh < 3; kh++) {
                const float* row = &tr[(2 * orow + kh) * 17];
                #pragma unroll
                for (int kw = 0; kw < 3; kw++) {
                    float wv = ws[((ic0 + icl) * 9 + kh * 3 + kw) * 32 + oc];
                    #pragma unroll
                    for (int ow = 0; ow < 8; ow++)
                        acc[ow] += row[2 * ow + kw] * wv;
                }
            }
        }
    }
    float ls = 0.f, ls2 = 0.f;
    size_t ybase = ((size_t)(b * OC + oc) * OH + (oh0 + orow)) * OW + ow0;
    #pragma unroll
    for (int ow = 0; ow < 8; ow++) {
        float v = acc[ow];
        ls += v; ls2 += v * v;
        g_y[ybase + ow] = v;
    }
    atomicAdd(&ssum[oc], ls);
    atomicAdd(&ssum2[oc], ls2);
    __syncthreads();
    if (tid < OC) {
        atomicAdd(&g_bnsum[tid], ssum[tid]);
        atomicAdd(&g_bnsum2[tid], ssum2[tid]);
    }
}

// ---------------- 7. finalize BN scale/shift ----------------
__global__ void k_bnfin(const float* __restrict__ gam, const float* __restrict__ bet) {
    int c = threadIdx.x;
    float cnt = (float)(B * OH * OW);
    float mu  = g_bnsum[c] / cnt;
    float var = g_bnsum2[c] / cnt - mu * mu;
    float sc  = gam[c] * rsqrtf(var + 1e-3f);
    g_bns[c] = sc;
    g_bnb[c] = bet[c] - mu * sc;
}

// ---------------- 8. BN apply + SiLU ----------------
__global__ void k_out(float* __restrict__ out) {
    int i = blockIdx.x * blockDim.x + threadIdx.x;
    int ch = (i >> 12) & 31;   // 64*64 = 4096 per channel
    float v = g_y[i] * g_bns[ch] + g_bnb[ch];
    out[i] = v / (1.f + expf(-v));
}

// ---------------- launch ----------------
extern "C" void kernel_launch(void* const* d_in, const int* in_sizes, int n_in,
                              void* d_out, int out_size) {
    const float* x    = (const float*)d_in[0];
    const float* lw   = (const float*)d_in[1];
    const float* lb   = (const float*)d_in[2];
    const float* lsa  = (const float*)d_in[3];
    const float* cw   = (const float*)d_in[4];
    const float* cb   = (const float*)d_in[5];
    const float* gam  = (const float*)d_in[6];
    const float* bet  = (const float*)d_in[7];
    float* out = (float*)d_out;

    k_pool<<<B * C, 256>>>(x);
    k_svec<<<B, 512>>>();
    k_feat<<<(B * C) / 8, 256>>>();
    k_attn<<<(B * C) / 8, 256>>>(lw, lb);
    k_select<<<1, C>>>();
    k_xc<<<(B * HW) / 256, 256>>>(x);
    k_lsa<<<dim3(Wd / 16, H / 16, B), dim3(16, 16)>>>(lsa);
    k_zero<<<1, 32>>>();
    k_conv<<<dim3(OW / 8, OH / 8, B), 256>>>(cw, cb);
    k_bnfin<<<1, OC>>>(gam, bet);
    k_out<<<(B * OC * OH * OW) / 512, 512>>>(out);
}